// round 13
// baseline (speedup 1.0000x reference)
#include <cuda_runtime.h>
#include <cuda_fp16.h>
#include <math_constants.h>

#define Bn 64
#define Ln 4096
#define Nn 128
#define Fn 2049
#define FS 2056          // padded row stride for g_freq (bins)
#define N2h 2048
#define En 8
#define NSER (Bn * Nn)   // 8192
#define KSPLIT 8
#define KCH 257          // 8*257 = 2056 >= 2049

#define C_SQ 0.70710678118654752f
#define PADi(i) ((i) + ((i) >> 3))

// ---------------- scratch ----------------
__device__ __half  g_xt[(size_t)NSER * Ln];     // fp16 time scratch (fwd input / rec output)
__device__ __half  g_x16[(size_t)Bn * Ln * Nn]; // fp16 copy of x in [B,L,N] layout
__device__ __half2 g_freq[(size_t)NSER * FS];   // fp16 spectrum (re,im)
__device__ float   g_mean[NSER];
__device__ float   g_std[NSER];
__device__ float   g_magp[2][Fn * 64];          // n-split partials [half][f*64+b]
__device__ float   g_magT[Fn * 64];             // [f][b]
__device__ float   g_hp[KSPLIT * 64 * Fn];      // gemm partials [ks][b][j]
__device__ float   g_wmask[Bn * Fn];
__device__ int     g_bandOf[Fn];
__device__ float2  g_T[1025];   // T[i] = exp(-i*pi*i/2048), i=0..1024

struct cpx { float x, y; };
__device__ __forceinline__ cpx cmul(cpx a, cpx b) {
    return cpx{a.x * b.x - a.y * b.y, a.x * b.y + a.y * b.x};
}
__device__ __forceinline__ void fft2p(cpx& a, cpx& b) {
    cpx t{a.x - b.x, a.y - b.y};
    a = cpx{a.x + b.x, a.y + b.y};
    b = t;
}
template <int CONJ> __device__ __forceinline__ cpx mul_mi(cpx a) {
    return CONJ ? cpx{-a.y, a.x} : cpx{a.y, -a.x};
}
template <int CONJ> __device__ __forceinline__ cpx mul_w81(cpx a) {
    return CONJ ? cpx{C_SQ * (a.x - a.y), C_SQ * (a.y + a.x)}
                : cpx{C_SQ * (a.x + a.y), C_SQ * (a.y - a.x)};
}
template <int CONJ> __device__ __forceinline__ cpx mul_w83(cpx a) {
    return CONJ ? cpx{-C_SQ * (a.x + a.y), C_SQ * (a.x - a.y)}
                : cpx{C_SQ * (a.y - a.x), -C_SQ * (a.x + a.y)};
}

// radix-8 DIF butterfly; outputs bit-reversed: y_r = a[brev(r)], brev = 0,4,2,6,1,5,3,7
template <int CONJ> __device__ __forceinline__ void dft8(cpx a[8]) {
    fft2p(a[0], a[4]); fft2p(a[1], a[5]); fft2p(a[2], a[6]); fft2p(a[3], a[7]);
    a[5] = mul_w81<CONJ>(a[5]);
    a[6] = mul_mi<CONJ>(a[6]);
    a[7] = mul_w83<CONJ>(a[7]);
    fft2p(a[0], a[2]); fft2p(a[1], a[3]);
    a[3] = mul_mi<CONJ>(a[3]);
    fft2p(a[4], a[6]); fft2p(a[5], a[7]);
    a[7] = mul_mi<CONJ>(a[7]);
    fft2p(a[0], a[1]); fft2p(a[2], a[3]); fft2p(a[4], a[5]); fft2p(a[6], a[7]);
}
template <int CONJ> __device__ __forceinline__ void dft4(cpx a[4]) {
    fft2p(a[0], a[2]); fft2p(a[1], a[3]);
    a[3] = mul_mi<CONJ>(a[3]);
    fft2p(a[0], a[1]); fft2p(a[2], a[3]);
}

__device__ __forceinline__ float2 tw_lookup_g(int idx) {
    if (idx <= 1024) return g_T[idx];
    float2 u = g_T[2048 - idx];
    return make_float2(-u.x, u.y);
}

#define ST8(RE, IM, IDX0, STRIDE)                                              \
    do {                                                                       \
        cpx y;                                                                 \
        y = a[0];              RE[PADi((IDX0))] = y.x; IM[PADi((IDX0))] = y.y; \
        y = cmul(a[4], w1);    RE[PADi((IDX0) + (STRIDE))] = y.x; IM[PADi((IDX0) + (STRIDE))] = y.y; \
        y = cmul(a[2], w2);    RE[PADi((IDX0) + 2*(STRIDE))] = y.x; IM[PADi((IDX0) + 2*(STRIDE))] = y.y; \
        y = cmul(a[6], w3);    RE[PADi((IDX0) + 3*(STRIDE))] = y.x; IM[PADi((IDX0) + 3*(STRIDE))] = y.y; \
        y = cmul(a[1], w4);    RE[PADi((IDX0) + 4*(STRIDE))] = y.x; IM[PADi((IDX0) + 4*(STRIDE))] = y.y; \
        y = cmul(a[5], w5);    RE[PADi((IDX0) + 5*(STRIDE))] = y.x; IM[PADi((IDX0) + 5*(STRIDE))] = y.y; \
        y = cmul(a[3], w6);    RE[PADi((IDX0) + 6*(STRIDE))] = y.x; IM[PADi((IDX0) + 6*(STRIDE))] = y.y; \
        y = cmul(a[7], w7);    RE[PADi((IDX0) + 7*(STRIDE))] = y.x; IM[PADi((IDX0) + 7*(STRIDE))] = y.y; \
    } while (0)

#define MAKE_POWERS(base)                                                      \
    cpx w1 = base;                                                             \
    cpx w2 = cmul(w1, w1); cpx w3 = cmul(w2, w1); cpx w4 = cmul(w2, w2);       \
    cpx w5 = cmul(w4, w1); cpx w6 = cmul(w3, w3); cpx w7 = cmul(w4, w3)

// in-place passes 1..2 (radix-8) on single SoA buffer: read->sync->write->sync
template <int CONJ>
__device__ __forceinline__ void fft_passes_12_ip(float* sR, float* sI, int t) {
    // pass1 (s=8): read t+256r, write q+64p+8r   (p=t>>3, q=t&7)
    {
        cpx a[8];
        #pragma unroll
        for (int r = 0; r < 8; r++) {
            int i = PADi(t + 256 * r);
            a[r] = cpx{sR[i], sI[i]};
        }
        __syncthreads();
        dft8<CONJ>(a);
        int p = t >> 3, q = t & 7;
        float2 wb = g_T[16 * p];
        cpx base{wb.x, CONJ ? -wb.y : wb.y};
        MAKE_POWERS(base);
        ST8(sR, sI, q + 64 * p, 8);
    }
    __syncthreads();
    // pass2 (s=64): read q+64p+256r, write q+512p+64r   (q=t&63, p=t>>6)
    {
        cpx a[8];
        int q = t & 63, p = t >> 6;
        #pragma unroll
        for (int r = 0; r < 8; r++) {
            int i = PADi(q + 64 * p + 256 * r);
            a[r] = cpx{sR[i], sI[i]};
        }
        __syncthreads();
        dft8<CONJ>(a);
        float2 wb = g_T[128 * p];
        cpx base{wb.x, CONJ ? -wb.y : wb.y};
        MAKE_POWERS(base);
        ST8(sR, sI, q + 512 * p, 64);
    }
    __syncthreads();
}

// ---------------- K0: twiddle table + band indices ----------------
__global__ void k_init(const float* __restrict__ bb) {
    int k = blockIdx.x * 256 + threadIdx.x;
    if (k <= 1024) {
        float s, c;
        sincosf(CUDART_PI_F * (float)k / 2048.f, &s, &c);
        g_T[k] = make_float2(c, -s);
    }
    if (blockIdx.x == 0) {
        __shared__ int idx[9];
        if (threadIdx.x == 0) {
            float v[7];
            #pragma unroll
            for (int i = 0; i < 7; i++) v[i] = 1.f / (1.f + expf(-bb[i]));
            for (int i = 1; i < 7; i++) {
                float key = v[i]; int j = i - 1;
                while (j >= 0 && v[j] > key) { v[j + 1] = v[j]; j--; }
                v[j + 1] = key;
            }
            idx[0] = 0;
            for (int e = 1; e < 8; e++) {
                int t = (int)(v[e - 1] * 2049.0f);
                idx[e] = min(max(t, 0), 2049);
            }
            idx[8] = 2049;
        }
        __syncthreads();
        for (int f = threadIdx.x; f < Fn; f += 256) {
            int e = 0;
            #pragma unroll
            for (int t = 0; t < 8; t++)
                if (f >= idx[t] && f < idx[t + 1]) { e = t; break; }
            g_bandOf[f] = e;
        }
    }
}

// ---------------- K1: transpose x -> g_xt fp16 [B,N,L]; also fp16 copy g_x16 [B,L,N] ----------------
__global__ void k_transpose_in(const float* __restrict__ x) {
    __shared__ float tile[32][33];
    int b = blockIdx.z;
    int l0 = blockIdx.x * 32, n0 = blockIdx.y * 32;
    int tx = threadIdx.x, ty = threadIdx.y;  // 8 x 32
    size_t elem = ((size_t)(b * Ln + l0 + ty)) * Nn + n0 + 4 * tx;
    const float4* x4 = (const float4*)x;
    float4 v = x4[elem >> 2];
    tile[ty][4 * tx + 0] = v.x;
    tile[ty][4 * tx + 1] = v.y;
    tile[ty][4 * tx + 2] = v.z;
    tile[ty][4 * tx + 3] = v.w;
    // fp16 passthrough copy (same layout as x)
    {
        __half2 c0 = __floats2half2_rn(v.x, v.y);
        __half2 c1 = __floats2half2_rn(v.z, v.w);
        uint2 pc;
        pc.x = *reinterpret_cast<unsigned*>(&c0);
        pc.y = *reinterpret_cast<unsigned*>(&c1);
        *reinterpret_cast<uint2*>(g_x16 + elem) = pc;
    }
    __syncthreads();
    __half2 h0 = __floats2half2_rn(tile[4 * tx + 0][ty], tile[4 * tx + 1][ty]);
    __half2 h1 = __floats2half2_rn(tile[4 * tx + 2][ty], tile[4 * tx + 3][ty]);
    uint2 pk;
    pk.x = *reinterpret_cast<unsigned*>(&h0);
    pk.y = *reinterpret_cast<unsigned*>(&h1);
    size_t base = ((size_t)(b * Nn + n0 + ty)) * Ln + l0 + 4 * tx;
    *reinterpret_cast<uint2*>(g_xt + base) = pk;
}

// ---------------- K2: per-series mean/var + rfft -> fp16 spectrum ----------------
__global__ __launch_bounds__(256) void k_fwd() {
    __shared__ float sR[2304], sI[2304];
    __shared__ float sred[16];
    int series = blockIdx.x;
    int t = threadIdx.x;
    const __half2* row = (const __half2*)(g_xt + (size_t)series * Ln);

    cpx a[8];
    float s1 = 0.f, s2 = 0.f;
    #pragma unroll
    for (int r = 0; r < 8; r++) {
        float2 v = __half22float2(row[t + 256 * r]);
        a[r] = cpx{v.x, v.y};
        s1 += v.x + v.y;
        s2 += v.x * v.x + v.y * v.y;
    }
    #pragma unroll
    for (int off = 16; off; off >>= 1) {
        s1 += __shfl_down_sync(~0u, s1, off);
        s2 += __shfl_down_sync(~0u, s2, off);
    }
    if ((t & 31) == 0) { sred[t >> 5] = s1; sred[8 + (t >> 5)] = s2; }

    // pass0: regs -> smem (writes only; no prior smem reads)
    dft8<0>(a);
    {
        float2 wb = g_T[2 * t];
        cpx base{wb.x, wb.y};
        MAKE_POWERS(base);
        ST8(sR, sI, 8 * t, 1);
    }
    __syncthreads();
    if (t == 0) {
        float aa = 0.f, bb = 0.f;
        #pragma unroll
        for (int w = 0; w < 8; w++) { aa += sred[w]; bb += sred[8 + w]; }
        float mean = aa * (1.f / 4096.f);
        float var = bb * (1.f / 4096.f) - mean * mean + 1e-6f;
        g_mean[series] = mean;
        g_std[series]  = sqrtf(fmaxf(var, 0.f));
    }

    fft_passes_12_ip<0>(sR, sI, t);

    // pass3: radix-4, in-place element-wise (read set == write set per thread)
    #pragma unroll
    for (int uu = 0; uu < 2; uu++) {
        int u = t + 256 * uu;
        cpx c4[4];
        #pragma unroll
        for (int r = 0; r < 4; r++) {
            int i = PADi(u + 512 * r);
            c4[r] = cpx{sR[i], sI[i]};
        }
        dft4<0>(c4);
        sR[PADi(u)]        = c4[0].x; sI[PADi(u)]        = c4[0].y;
        sR[PADi(u + 512)]  = c4[2].x; sI[PADi(u + 512)]  = c4[2].y;
        sR[PADi(u + 1024)] = c4[1].x; sI[PADi(u + 1024)] = c4[1].y;
        sR[PADi(u + 1536)] = c4[3].x; sI[PADi(u + 1536)] = c4[3].y;
    }
    __syncthreads();

    // untangle packed FFT -> rfft bins, store fp16
    __half2* out = g_freq + (size_t)series * FS;
    for (int k = t; k < Fn; k += 256) {
        int ik = PADi(k & (N2h - 1));
        int imk = PADi((N2h - k) & (N2h - 1));
        cpx zk{sR[ik], sI[ik]};
        cpx zmk{sR[imk], sI[imk]};
        float2 A = make_float2(0.5f * (zk.x + zmk.x), 0.5f * (zk.y - zmk.y));
        float dx = zk.x - zmk.x, dy = zk.y + zmk.y;
        float2 Bv = make_float2(0.5f * dy, -0.5f * dx);
        float2 tw = tw_lookup_g(k);
        out[k] = __floats2half2_rn(A.x + tw.x * Bv.x - tw.y * Bv.y,
                                   A.y + tw.x * Bv.y + tw.y * Bv.x);
    }
}

// ---------------- K3: partial mag over n-half ----------------
__global__ __launch_bounds__(256) void k_mag() {
    int f = blockIdx.x * 256 + threadIdx.x;
    int b = blockIdx.y;
    int h = blockIdx.z;   // n half: 0 or 1
    if (f >= Fn) return;
    const __half2* base = g_freq + (size_t)b * Nn * FS + (size_t)h * 64 * FS + f;
    float acc[8];
    #pragma unroll
    for (int j = 0; j < 8; j++) acc[j] = 0.f;
    #pragma unroll 2
    for (int n0 = 0; n0 < 64; n0 += 8) {
        #pragma unroll
        for (int j = 0; j < 8; j++) {
            float2 v = __half22float2(base[(size_t)(n0 + j) * FS]);
            acc[j] += sqrtf(v.x * v.x + v.y * v.y);
        }
    }
    float s = ((acc[0] + acc[1]) + (acc[2] + acc[3])) +
              ((acc[4] + acc[5]) + (acc[6] + acc[7]));
    g_magp[h][f * 64 + b] = s;
}

// ---------------- K3b: merge partials -> magT ----------------
__global__ __launch_bounds__(256) void k_magred() {
    int i = blockIdx.x * 256 + threadIdx.x;
    if (i < Fn * 64)
        g_magT[i] = (g_magp[0][i] + g_magp[1][i]) * (1.f / 128.f);
}

// ---------------- K4a: GEMM partials, K-split ----------------
__global__ __launch_bounds__(256) void k_gemm1a(const float* __restrict__ w1) {
    int tid = threadIdx.x;
    int j = blockIdx.x * 64 + (tid & 63);
    int bg = tid >> 6;
    int ks = blockIdx.y;
    int kbeg = ks * KCH;
    int kend = min(kbeg + KCH, Fn);
    bool jok = (j < Fn);

    float acc[16];
    #pragma unroll
    for (int i = 0; i < 16; i++) acc[i] = 0.f;

    const float4* magT4 = (const float4*)g_magT;
    #pragma unroll 2
    for (int k = kbeg; k < kend; k++) {
        float wv = jok ? __ldg(&w1[(size_t)k * Fn + j]) : 0.f;
        const float4* mrow = magT4 + ((size_t)k << 4) + (bg << 2);
        float4 m0 = mrow[0], m1 = mrow[1], m2 = mrow[2], m3 = mrow[3];
        acc[0]  = fmaf(m0.x, wv, acc[0]);  acc[1]  = fmaf(m0.y, wv, acc[1]);
        acc[2]  = fmaf(m0.z, wv, acc[2]);  acc[3]  = fmaf(m0.w, wv, acc[3]);
        acc[4]  = fmaf(m1.x, wv, acc[4]);  acc[5]  = fmaf(m1.y, wv, acc[5]);
        acc[6]  = fmaf(m1.z, wv, acc[6]);  acc[7]  = fmaf(m1.w, wv, acc[7]);
        acc[8]  = fmaf(m2.x, wv, acc[8]);  acc[9]  = fmaf(m2.y, wv, acc[9]);
        acc[10] = fmaf(m2.z, wv, acc[10]); acc[11] = fmaf(m2.w, wv, acc[11]);
        acc[12] = fmaf(m3.x, wv, acc[12]); acc[13] = fmaf(m3.y, wv, acc[13]);
        acc[14] = fmaf(m3.z, wv, acc[14]); acc[15] = fmaf(m3.w, wv, acc[15]);
    }
    if (jok) {
        #pragma unroll
        for (int i = 0; i < 16; i++) {
            int b = 16 * bg + i;
            g_hp[((size_t)(ks * 64 + b)) * Fn + j] = acc[i];
        }
    }
}

// ---------------- K5: partial-reduce + bias + relu + logits -> softmax -> wmask ----------------
__global__ __launch_bounds__(256) void k_gate2(const float* __restrict__ b1,
                                               const float* __restrict__ w2,
                                               const float* __restrict__ b2) {
    __shared__ float slog[8];
    __shared__ float sw[8];
    int b = blockIdx.x;
    int tid = threadIdx.x, warp = tid >> 5, lane = tid & 31;
    float part = 0.f;
    for (int k = lane; k < Fn; k += 32) {
        float s = b1[k];
        #pragma unroll
        for (int ks = 0; ks < KSPLIT; ks++)
            s += g_hp[((size_t)(ks * 64 + b)) * Fn + k];
        part += fmaxf(s, 0.f) * w2[k * En + warp];
    }
    #pragma unroll
    for (int off = 16; off; off >>= 1) part += __shfl_down_sync(~0u, part, off);
    if (lane == 0) slog[warp] = part + b2[warp];
    __syncthreads();
    if (tid == 0) {
        float mx = -1e30f;
        for (int e = 0; e < 8; e++) mx = fmaxf(mx, slog[e]);
        float s = 0.f, ex[8];
        for (int e = 0; e < 8; e++) { ex[e] = expf(slog[e] - mx); s += ex[e]; }
        float inv = 1.f / s;
        for (int e = 0; e < 8; e++) sw[e] = ex[e] * inv;
    }
    __syncthreads();
    for (int f = tid; f < Fn; f += 256)
        g_wmask[b * Fn + f] = sw[g_bandOf[f]];
}

// ---------------- K6: filter + irfft -> g_xt fp16 ----------------
__global__ __launch_bounds__(256) void k_inv() {
    __shared__ float sR[2304], sI[2304];
    int series = blockIdx.x;
    int b = series >> 7;
    int t = threadIdx.x;
    const __half2* Xg = g_freq + (size_t)series * FS;
    const float*   wm = g_wmask + b * Fn;

    // stage filtered bins 0..2047 (bin 2048 folded in repack below via direct load)
    for (int k = t; k < 2048; k += 256) {
        float2 v = __half22float2(Xg[k]);
        float w = wm[k];
        int i = PADi(k);
        sR[i] = v.x * w;
        sI[i] = v.y * w;
    }
    __syncthreads();

    // repack rfft bins -> Z[0..2047] in place (thread owning k<=1024 updates k and 2048-k)
    for (int k = t; k <= 1024; k += 256) {
        int ik = PADi(k);
        cpx Xk{sR[ik], sI[ik]};
        cpx Xmk;
        if (k == 0) {
            float2 v = __half22float2(Xg[2048]);
            float w = wm[2048];
            Xmk = cpx{v.x * w, v.y * w};
        } else {
            int imk0 = PADi(2048 - k);
            Xmk = cpx{sR[imk0], sI[imk0]};
        }
        float2 A = make_float2(0.5f * (Xk.x + Xmk.x), 0.5f * (Xk.y - Xmk.y));
        float dx = Xk.x - Xmk.x, dy = Xk.y + Xmk.y;
        float2 tw = g_T[k];          // (cos, -sin)
        float c = tw.x, sn = -tw.y;
        float2 Bc = make_float2(0.5f * (c * dx - sn * dy), 0.5f * (c * dy + sn * dx));
        sR[ik] = A.x - Bc.y;
        sI[ik] = A.y + Bc.x;
        if (k >= 1 && k < 1024) {
            int imk = PADi(2048 - k);
            sR[imk] = A.x + Bc.y;
            sI[imk] = Bc.x - A.y;
        }
    }
    __syncthreads();

    // pass0 (s=1): read t+256r, write 8t+r  — in-place read->sync->write
    {
        cpx a[8];
        #pragma unroll
        for (int r = 0; r < 8; r++) {
            int i = PADi(t + 256 * r);
            a[r] = cpx{sR[i], sI[i]};
        }
        __syncthreads();
        dft8<1>(a);
        float2 wb = g_T[2 * t];
        cpx base{wb.x, -wb.y};
        MAKE_POWERS(base);
        ST8(sR, sI, 8 * t, 1);
    }
    __syncthreads();

    fft_passes_12_ip<1>(sR, sI, t);

    // pass3: radix-4, read from smem -> write global fp16 (scale + mean)
    __half2* outrow = (__half2*)(g_xt + (size_t)series * Ln);
    float mean = g_mean[series];
    float stdv = g_std[series] * (1.f / 2048.f);
    #pragma unroll
    for (int uu = 0; uu < 2; uu++) {
        int u = t + 256 * uu;
        cpx c4[4];
        #pragma unroll
        for (int r = 0; r < 4; r++) {
            int i = PADi(u + 512 * r);
            c4[r] = cpx{sR[i], sI[i]};
        }
        dft4<1>(c4);
        outrow[u]        = __floats2half2_rn(fmaf(c4[0].x, stdv, mean), fmaf(c4[0].y, stdv, mean));
        outrow[u + 512]  = __floats2half2_rn(fmaf(c4[2].x, stdv, mean), fmaf(c4[2].y, stdv, mean));
        outrow[u + 1024] = __floats2half2_rn(fmaf(c4[1].x, stdv, mean), fmaf(c4[1].y, stdv, mean));
        outrow[u + 1536] = __floats2half2_rn(fmaf(c4[3].x, stdv, mean), fmaf(c4[3].y, stdv, mean));
    }
}

// ---------------- K7: out[b,l,n] = x16[b,l,n] + rec[b,n,l] ----------------
__global__ void k_transpose_out(float* __restrict__ out) {
    __shared__ float tile[32][33];
    int b = blockIdx.z;
    int l0 = blockIdx.x * 32, n0 = blockIdx.y * 32;
    int tx = threadIdx.x, ty = threadIdx.y;  // 8 x 32
    size_t gbase = ((size_t)(b * Nn + n0 + ty)) * Ln + l0 + 4 * tx;
    uint2 pk = *reinterpret_cast<const uint2*>(g_xt + gbase);
    float2 v0 = __half22float2(*reinterpret_cast<__half2*>(&pk.x));
    float2 v1 = __half22float2(*reinterpret_cast<__half2*>(&pk.y));
    tile[ty][4 * tx + 0] = v0.x;
    tile[ty][4 * tx + 1] = v0.y;
    tile[ty][4 * tx + 2] = v1.x;
    tile[ty][4 * tx + 3] = v1.y;
    __syncthreads();
    size_t elem = ((size_t)(b * Ln + l0 + ty)) * Nn + n0 + 4 * tx;
    uint2 px = *reinterpret_cast<const uint2*>(g_x16 + elem);
    float2 x0 = __half22float2(*reinterpret_cast<__half2*>(&px.x));
    float2 x1 = __half22float2(*reinterpret_cast<__half2*>(&px.y));
    float4 w;
    w.x = x0.x + tile[4 * tx + 0][ty];
    w.y = x0.y + tile[4 * tx + 1][ty];
    w.z = x1.x + tile[4 * tx + 2][ty];
    w.w = x1.y + tile[4 * tx + 3][ty];
    ((float4*)out)[elem >> 2] = w;
}

extern "C" void kernel_launch(void* const* d_in, const int* in_sizes, int n_in,
                              void* d_out, int out_size) {
    const float* x  = (const float*)d_in[0];
    const float* bb = (const float*)d_in[1];
    const float* w1 = (const float*)d_in[2];
    const float* b1 = (const float*)d_in[3];
    const float* w2 = (const float*)d_in[4];
    const float* b2 = (const float*)d_in[5];
    float* out = (float*)d_out;

    dim3 tb(8, 32);
    k_init<<<5, 256>>>(bb);
    k_transpose_in<<<dim3(128, 4, 64), tb>>>(x);
    k_fwd<<<NSER, 256>>>();
    k_mag<<<dim3(9, 64, 2), 256>>>();
    k_magred<<<513, 256>>>();
    k_gemm1a<<<dim3(33, KSPLIT), 256>>>(w1);
    k_gate2<<<64, 256>>>(b1, w2, b2);
    k_inv<<<NSER, 256>>>();
    k_transpose_out<<<dim3(128, 4, 64), tb>>>(out);
}

// round 14
// speedup vs baseline: 1.1072x; 1.1072x over previous
#include <cuda_runtime.h>
#include <cuda_fp16.h>
#include <math_constants.h>

#define Bn 64
#define Ln 4096
#define Nn 128
#define Fn 2049
#define FS 2056          // padded row stride for g_freq (bins)
#define N2h 2048
#define En 8
#define NSER (Bn * Nn)   // 8192
#define KSPLIT 8
#define KCH 257          // 8*257 = 2056 >= 2049

#define C_SQ 0.70710678118654752f
#define PADi(i) ((i) + ((i) >> 3))

// ---------------- scratch ----------------
__device__ __half  g_xt[(size_t)NSER * Ln];     // fp16 time scratch (fwd input / rec output)
__device__ __half2 g_freq[(size_t)NSER * FS];   // fp16 spectrum (re,im)
__device__ float   g_mean[NSER];
__device__ float   g_std[NSER];
__device__ float   g_magp[2][Fn * 64];          // n-split partials [half][f*64+b]
__device__ float   g_magT[Fn * 64];             // [f][b]
__device__ float   g_hp[KSPLIT * 64 * Fn];      // gemm partials [ks][b][j]
__device__ float   g_h[Bn * Fn];
__device__ float   g_wmask[Bn * Fn];
__device__ int     g_bandOf[Fn];
__device__ float2  g_T[1025];   // T[i] = exp(-i*pi*i/2048), i=0..1024

struct cpx { float x, y; };
__device__ __forceinline__ cpx cmul(cpx a, cpx b) {
    return cpx{a.x * b.x - a.y * b.y, a.x * b.y + a.y * b.x};
}
__device__ __forceinline__ void fft2p(cpx& a, cpx& b) {
    cpx t{a.x - b.x, a.y - b.y};
    a = cpx{a.x + b.x, a.y + b.y};
    b = t;
}
template <int CONJ> __device__ __forceinline__ cpx mul_mi(cpx a) {
    return CONJ ? cpx{-a.y, a.x} : cpx{a.y, -a.x};
}
template <int CONJ> __device__ __forceinline__ cpx mul_w81(cpx a) {
    return CONJ ? cpx{C_SQ * (a.x - a.y), C_SQ * (a.y + a.x)}
                : cpx{C_SQ * (a.x + a.y), C_SQ * (a.y - a.x)};
}
template <int CONJ> __device__ __forceinline__ cpx mul_w83(cpx a) {
    return CONJ ? cpx{-C_SQ * (a.x + a.y), C_SQ * (a.x - a.y)}
                : cpx{C_SQ * (a.y - a.x), -C_SQ * (a.x + a.y)};
}

// radix-8 DIF butterfly; outputs bit-reversed: y_r = a[brev(r)], brev = 0,4,2,6,1,5,3,7
template <int CONJ> __device__ __forceinline__ void dft8(cpx a[8]) {
    fft2p(a[0], a[4]); fft2p(a[1], a[5]); fft2p(a[2], a[6]); fft2p(a[3], a[7]);
    a[5] = mul_w81<CONJ>(a[5]);
    a[6] = mul_mi<CONJ>(a[6]);
    a[7] = mul_w83<CONJ>(a[7]);
    fft2p(a[0], a[2]); fft2p(a[1], a[3]);
    a[3] = mul_mi<CONJ>(a[3]);
    fft2p(a[4], a[6]); fft2p(a[5], a[7]);
    a[7] = mul_mi<CONJ>(a[7]);
    fft2p(a[0], a[1]); fft2p(a[2], a[3]); fft2p(a[4], a[5]); fft2p(a[6], a[7]);
}
template <int CONJ> __device__ __forceinline__ void dft4(cpx a[4]) {
    fft2p(a[0], a[2]); fft2p(a[1], a[3]);
    a[3] = mul_mi<CONJ>(a[3]);
    fft2p(a[0], a[1]); fft2p(a[2], a[3]);
}

__device__ __forceinline__ float2 tw_lookup_g(int idx) {
    if (idx <= 1024) return g_T[idx];
    float2 u = g_T[2048 - idx];
    return make_float2(-u.x, u.y);
}

#define ST8(RE, IM, IDX0, STRIDE)                                              \
    do {                                                                       \
        cpx y;                                                                 \
        y = a[0];              RE[PADi((IDX0))] = y.x; IM[PADi((IDX0))] = y.y; \
        y = cmul(a[4], w1);    RE[PADi((IDX0) + (STRIDE))] = y.x; IM[PADi((IDX0) + (STRIDE))] = y.y; \
        y = cmul(a[2], w2);    RE[PADi((IDX0) + 2*(STRIDE))] = y.x; IM[PADi((IDX0) + 2*(STRIDE))] = y.y; \
        y = cmul(a[6], w3);    RE[PADi((IDX0) + 3*(STRIDE))] = y.x; IM[PADi((IDX0) + 3*(STRIDE))] = y.y; \
        y = cmul(a[1], w4);    RE[PADi((IDX0) + 4*(STRIDE))] = y.x; IM[PADi((IDX0) + 4*(STRIDE))] = y.y; \
        y = cmul(a[5], w5);    RE[PADi((IDX0) + 5*(STRIDE))] = y.x; IM[PADi((IDX0) + 5*(STRIDE))] = y.y; \
        y = cmul(a[3], w6);    RE[PADi((IDX0) + 6*(STRIDE))] = y.x; IM[PADi((IDX0) + 6*(STRIDE))] = y.y; \
        y = cmul(a[7], w7);    RE[PADi((IDX0) + 7*(STRIDE))] = y.x; IM[PADi((IDX0) + 7*(STRIDE))] = y.y; \
    } while (0)

#define MAKE_POWERS(base)                                                      \
    cpx w1 = base;                                                             \
    cpx w2 = cmul(w1, w1); cpx w3 = cmul(w2, w1); cpx w4 = cmul(w2, w2);       \
    cpx w5 = cmul(w4, w1); cpx w6 = cmul(w3, w3); cpx w7 = cmul(w4, w3)

template <int CONJ>
__device__ __forceinline__ void fft_passes_123(
    float* sRa, float* sIa, float* sRb, float* sIb, int t) {
    // pass1: B -> A   (s=8)
    {
        cpx a[8];
        #pragma unroll
        for (int r = 0; r < 8; r++) {
            int i = PADi(t + 256 * r);
            a[r] = cpx{sRb[i], sIb[i]};
        }
        dft8<CONJ>(a);
        int p = t >> 3, q = t & 7;
        float2 wb = g_T[16 * p];
        cpx base{wb.x, CONJ ? -wb.y : wb.y};
        MAKE_POWERS(base);
        int i0 = q + 64 * p;
        ST8(sRa, sIa, i0, 8);
    }
    __syncthreads();
    // pass2: A -> B   (s=64)
    {
        cpx a[8];
        int q = t & 63, p = t >> 6;
        #pragma unroll
        for (int r = 0; r < 8; r++) {
            int i = PADi(q + 64 * p + 256 * r);
            a[r] = cpx{sRa[i], sIa[i]};
        }
        dft8<CONJ>(a);
        float2 wb = g_T[128 * p];
        cpx base{wb.x, CONJ ? -wb.y : wb.y};
        MAKE_POWERS(base);
        int i0 = q + 512 * p;
        ST8(sRb, sIb, i0, 64);
    }
    __syncthreads();
}

// ---------------- K0: twiddle table + band indices ----------------
__global__ void k_init(const float* __restrict__ bb) {
    int k = blockIdx.x * 256 + threadIdx.x;
    if (k <= 1024) {
        float s, c;
        sincosf(CUDART_PI_F * (float)k / 2048.f, &s, &c);
        g_T[k] = make_float2(c, -s);
    }
    if (blockIdx.x == 0) {
        __shared__ int idx[9];
        if (threadIdx.x == 0) {
            float v[7];
            #pragma unroll
            for (int i = 0; i < 7; i++) v[i] = 1.f / (1.f + expf(-bb[i]));
            for (int i = 1; i < 7; i++) {
                float key = v[i]; int j = i - 1;
                while (j >= 0 && v[j] > key) { v[j + 1] = v[j]; j--; }
                v[j + 1] = key;
            }
            idx[0] = 0;
            for (int e = 1; e < 8; e++) {
                int t = (int)(v[e - 1] * 2049.0f);
                idx[e] = min(max(t, 0), 2049);
            }
            idx[8] = 2049;
        }
        __syncthreads();
        for (int f = threadIdx.x; f < Fn; f += 256) {
            int e = 0;
            #pragma unroll
            for (int t = 0; t < 8; t++)
                if (f >= idx[t] && f < idx[t + 1]) { e = t; break; }
            g_bandOf[f] = e;
        }
    }
}

// ---------------- K1: transpose x [B,L,N] -> g_xt fp16 [B,N,L] ----------------
__global__ void k_transpose_in(const float* __restrict__ x) {
    __shared__ float tile[32][33];
    int b = blockIdx.z;
    int l0 = blockIdx.x * 32, n0 = blockIdx.y * 32;
    int tx = threadIdx.x, ty = threadIdx.y;  // 8 x 32
    const float4* x4 = (const float4*)x;
    float4 v = x4[(((size_t)(b * Ln + l0 + ty)) * Nn + n0 + 4 * tx) >> 2];
    tile[ty][4 * tx + 0] = v.x;
    tile[ty][4 * tx + 1] = v.y;
    tile[ty][4 * tx + 2] = v.z;
    tile[ty][4 * tx + 3] = v.w;
    __syncthreads();
    __half2 h0 = __floats2half2_rn(tile[4 * tx + 0][ty], tile[4 * tx + 1][ty]);
    __half2 h1 = __floats2half2_rn(tile[4 * tx + 2][ty], tile[4 * tx + 3][ty]);
    uint2 pk;
    pk.x = *reinterpret_cast<unsigned*>(&h0);
    pk.y = *reinterpret_cast<unsigned*>(&h1);
    size_t base = ((size_t)(b * Nn + n0 + ty)) * Ln + l0 + 4 * tx;
    *reinterpret_cast<uint2*>(g_xt + base) = pk;
}

// ---------------- K2: per-series mean/var + rfft -> fp16 spectrum ----------------
__global__ __launch_bounds__(256) void k_fwd() {
    __shared__ float sRa[2304], sIa[2304], sRb[2304], sIb[2304];
    __shared__ float sred[16];
    int series = blockIdx.x;
    int t = threadIdx.x;
    const __half2* row = (const __half2*)(g_xt + (size_t)series * Ln);

    cpx a[8];
    float s1 = 0.f, s2 = 0.f;
    #pragma unroll
    for (int r = 0; r < 8; r++) {
        float2 v = __half22float2(row[t + 256 * r]);
        a[r] = cpx{v.x, v.y};
        s1 += v.x + v.y;
        s2 += v.x * v.x + v.y * v.y;
    }
    #pragma unroll
    for (int off = 16; off; off >>= 1) {
        s1 += __shfl_down_sync(~0u, s1, off);
        s2 += __shfl_down_sync(~0u, s2, off);
    }
    if ((t & 31) == 0) { sred[t >> 5] = s1; sred[8 + (t >> 5)] = s2; }

    dft8<0>(a);
    {
        float2 wb = g_T[2 * t];
        cpx base{wb.x, wb.y};
        MAKE_POWERS(base);
        ST8(sRb, sIb, 8 * t, 1);
    }
    __syncthreads();
    if (t == 0) {
        float aa = 0.f, bb = 0.f;
        #pragma unroll
        for (int w = 0; w < 8; w++) { aa += sred[w]; bb += sred[8 + w]; }
        float mean = aa * (1.f / 4096.f);
        float var = bb * (1.f / 4096.f) - mean * mean + 1e-6f;
        g_mean[series] = mean;
        g_std[series]  = sqrtf(fmaxf(var, 0.f));
    }

    fft_passes_123<0>(sRa, sIa, sRb, sIb, t);

    // pass3: radix-4, B -> A
    #pragma unroll
    for (int uu = 0; uu < 2; uu++) {
        int u = t + 256 * uu;
        cpx c4[4];
        #pragma unroll
        for (int r = 0; r < 4; r++) {
            int i = PADi(u + 512 * r);
            c4[r] = cpx{sRb[i], sIb[i]};
        }
        dft4<0>(c4);
        sRa[PADi(u)]        = c4[0].x; sIa[PADi(u)]        = c4[0].y;
        sRa[PADi(u + 512)]  = c4[2].x; sIa[PADi(u + 512)]  = c4[2].y;
        sRa[PADi(u + 1024)] = c4[1].x; sIa[PADi(u + 1024)] = c4[1].y;
        sRa[PADi(u + 1536)] = c4[3].x; sIa[PADi(u + 1536)] = c4[3].y;
    }
    __syncthreads();

    // untangle packed FFT -> rfft bins, store fp16
    __half2* out = g_freq + (size_t)series * FS;
    for (int k = t; k < Fn; k += 256) {
        int ik = PADi(k & (N2h - 1));
        int imk = PADi((N2h - k) & (N2h - 1));
        cpx zk{sRa[ik], sIa[ik]};
        cpx zmk{sRa[imk], sIa[imk]};
        float2 A = make_float2(0.5f * (zk.x + zmk.x), 0.5f * (zk.y - zmk.y));
        float dx = zk.x - zmk.x, dy = zk.y + zmk.y;
        float2 Bv = make_float2(0.5f * dy, -0.5f * dx);
        float2 tw = tw_lookup_g(k);
        out[k] = __floats2half2_rn(A.x + tw.x * Bv.x - tw.y * Bv.y,
                                   A.y + tw.x * Bv.y + tw.y * Bv.x);
    }
}

// ---------------- K3: partial mag over n-half (single-bin variant) ----------------
__global__ __launch_bounds__(256) void k_mag() {
    int f = blockIdx.x * 256 + threadIdx.x;
    int b = blockIdx.y;
    int h = blockIdx.z;   // n half: 0 or 1
    if (f >= Fn) return;
    const __half2* base = g_freq + (size_t)b * Nn * FS + (size_t)h * 64 * FS + f;
    float acc[8];
    #pragma unroll
    for (int j = 0; j < 8; j++) acc[j] = 0.f;
    #pragma unroll 2
    for (int n0 = 0; n0 < 64; n0 += 8) {
        #pragma unroll
        for (int j = 0; j < 8; j++) {
            float2 v = __half22float2(base[(size_t)(n0 + j) * FS]);
            acc[j] += sqrtf(v.x * v.x + v.y * v.y);
        }
    }
    float s = ((acc[0] + acc[1]) + (acc[2] + acc[3])) +
              ((acc[4] + acc[5]) + (acc[6] + acc[7]));
    g_magp[h][f * 64 + b] = s;
}

// ---------------- K3b: merge partials -> magT ----------------
__global__ __launch_bounds__(256) void k_magred() {
    int i = blockIdx.x * 256 + threadIdx.x;
    if (i < Fn * 64)
        g_magT[i] = (g_magp[0][i] + g_magp[1][i]) * (1.f / 128.f);
}

// ---------------- K4a: GEMM partials, K-split ----------------
__global__ __launch_bounds__(256) void k_gemm1a(const float* __restrict__ w1) {
    int tid = threadIdx.x;
    int j = blockIdx.x * 64 + (tid & 63);
    int bg = tid >> 6;
    int ks = blockIdx.y;
    int kbeg = ks * KCH;
    int kend = min(kbeg + KCH, Fn);
    bool jok = (j < Fn);

    float acc[16];
    #pragma unroll
    for (int i = 0; i < 16; i++) acc[i] = 0.f;

    const float4* magT4 = (const float4*)g_magT;
    #pragma unroll 2
    for (int k = kbeg; k < kend; k++) {
        float wv = jok ? __ldg(&w1[(size_t)k * Fn + j]) : 0.f;
        const float4* mrow = magT4 + ((size_t)k << 4) + (bg << 2);
        float4 m0 = mrow[0], m1 = mrow[1], m2 = mrow[2], m3 = mrow[3];
        acc[0]  = fmaf(m0.x, wv, acc[0]);  acc[1]  = fmaf(m0.y, wv, acc[1]);
        acc[2]  = fmaf(m0.z, wv, acc[2]);  acc[3]  = fmaf(m0.w, wv, acc[3]);
        acc[4]  = fmaf(m1.x, wv, acc[4]);  acc[5]  = fmaf(m1.y, wv, acc[5]);
        acc[6]  = fmaf(m1.z, wv, acc[6]);  acc[7]  = fmaf(m1.w, wv, acc[7]);
        acc[8]  = fmaf(m2.x, wv, acc[8]);  acc[9]  = fmaf(m2.y, wv, acc[9]);
        acc[10] = fmaf(m2.z, wv, acc[10]); acc[11] = fmaf(m2.w, wv, acc[11]);
        acc[12] = fmaf(m3.x, wv, acc[12]); acc[13] = fmaf(m3.y, wv, acc[13]);
        acc[14] = fmaf(m3.z, wv, acc[14]); acc[15] = fmaf(m3.w, wv, acc[15]);
    }
    if (jok) {
        #pragma unroll
        for (int i = 0; i < 16; i++) {
            int b = 16 * bg + i;
            g_hp[((size_t)(ks * 64 + b)) * Fn + j] = acc[i];
        }
    }
}

// ---------------- K4b: reduce partials + bias + relu -> g_h ----------------
__global__ __launch_bounds__(256) void k_gemm1b(const float* __restrict__ b1) {
    int j = blockIdx.x * 256 + threadIdx.x;
    int b = blockIdx.y;
    if (j >= Fn) return;
    float s = 0.f;
    #pragma unroll
    for (int ks = 0; ks < KSPLIT; ks++)
        s += g_hp[((size_t)(ks * 64 + b)) * Fn + j];
    g_h[b * Fn + j] = fmaxf(s + b1[j], 0.f);
}

// ---------------- K5: logits -> softmax -> wmask ----------------
__global__ __launch_bounds__(256) void k_gate2(const float* __restrict__ w2,
                                               const float* __restrict__ b2) {
    __shared__ float slog[8];
    __shared__ float sw[8];
    int b = blockIdx.x;
    int tid = threadIdx.x, warp = tid >> 5, lane = tid & 31;
    float part = 0.f;
    for (int k = lane; k < Fn; k += 32)
        part += g_h[b * Fn + k] * w2[k * En + warp];
    #pragma unroll
    for (int off = 16; off; off >>= 1) part += __shfl_down_sync(~0u, part, off);
    if (lane == 0) slog[warp] = part + b2[warp];
    __syncthreads();
    if (tid == 0) {
        float mx = -1e30f;
        for (int e = 0; e < 8; e++) mx = fmaxf(mx, slog[e]);
        float s = 0.f, ex[8];
        for (int e = 0; e < 8; e++) { ex[e] = expf(slog[e] - mx); s += ex[e]; }
        float inv = 1.f / s;
        for (int e = 0; e < 8; e++) sw[e] = ex[e] * inv;
    }
    __syncthreads();
    for (int f = tid; f < Fn; f += 256)
        g_wmask[b * Fn + f] = sw[g_bandOf[f]];
}

// ---------------- K6: filter + irfft -> g_xt fp16 ----------------
__global__ __launch_bounds__(256) void k_inv() {
    __shared__ float sRa[2304], sIa[2304], sRb[2304], sIb[2304];
    int series = blockIdx.x;
    int b = series >> 7;
    int t = threadIdx.x;
    const __half2* Xg = g_freq + (size_t)series * FS;
    const float*   wm = g_wmask + b * Fn;

    // fused filter + repack: rfft bins -> Z[0..2047]
    for (int k = t; k <= 1024; k += 256) {
        float2 vk = __half22float2(Xg[k]);
        float wk = wm[k];
        cpx Xk{vk.x * wk, vk.y * wk};
        int km = 2048 - k;
        float2 vm = __half22float2(Xg[km]);
        float wmk = wm[km];
        cpx Xmk{vm.x * wmk, vm.y * wmk};
        float2 A = make_float2(0.5f * (Xk.x + Xmk.x), 0.5f * (Xk.y - Xmk.y));
        float dx = Xk.x - Xmk.x, dy = Xk.y + Xmk.y;
        float2 tw = g_T[k];          // (cos, -sin)
        float c = tw.x, sn = -tw.y;
        float2 Bc = make_float2(0.5f * (c * dx - sn * dy), 0.5f * (c * dy + sn * dx));
        int ik = PADi(k);
        sRa[ik] = A.x - Bc.y;
        sIa[ik] = A.y + Bc.x;
        if (k >= 1 && k < 1024) {
            int imk = PADi(2048 - k);
            sRa[imk] = A.x + Bc.y;
            sIa[imk] = Bc.x - A.y;
        }
    }
    __syncthreads();

    // pass0: A -> B (inverse twiddles)
    {
        cpx a[8];
        #pragma unroll
        for (int r = 0; r < 8; r++) {
            int i = PADi(t + 256 * r);
            a[r] = cpx{sRa[i], sIa[i]};
        }
        dft8<1>(a);
        float2 wb = g_T[2 * t];
        cpx base{wb.x, -wb.y};
        MAKE_POWERS(base);
        ST8(sRb, sIb, 8 * t, 1);
    }
    __syncthreads();

    fft_passes_123<1>(sRa, sIa, sRb, sIb, t);

    // pass3: radix-4, B -> global fp16 (scale + mean)
    __half2* outrow = (__half2*)(g_xt + (size_t)series * Ln);
    float mean = g_mean[series];
    float stdv = g_std[series] * (1.f / 2048.f);
    #pragma unroll
    for (int uu = 0; uu < 2; uu++) {
        int u = t + 256 * uu;
        cpx c4[4];
        #pragma unroll
        for (int r = 0; r < 4; r++) {
            int i = PADi(u + 512 * r);
            c4[r] = cpx{sRb[i], sIb[i]};
        }
        dft4<1>(c4);
        outrow[u]        = __floats2half2_rn(fmaf(c4[0].x, stdv, mean), fmaf(c4[0].y, stdv, mean));
        outrow[u + 512]  = __floats2half2_rn(fmaf(c4[2].x, stdv, mean), fmaf(c4[2].y, stdv, mean));
        outrow[u + 1024] = __floats2half2_rn(fmaf(c4[1].x, stdv, mean), fmaf(c4[1].y, stdv, mean));
        outrow[u + 1536] = __floats2half2_rn(fmaf(c4[3].x, stdv, mean), fmaf(c4[3].y, stdv, mean));
    }
}

// ---------------- K7: out[b,l,n] = x[b,l,n] + rec[b,n,l] ----------------
__global__ void k_transpose_out(const float* __restrict__ x, float* __restrict__ out) {
    __shared__ float tile[32][33];
    int b = blockIdx.z;
    int l0 = blockIdx.x * 32, n0 = blockIdx.y * 32;
    int tx = threadIdx.x, ty = threadIdx.y;  // 8 x 32
    size_t gbase = ((size_t)(b * Nn + n0 + ty)) * Ln + l0 + 4 * tx;
    uint2 pk = *reinterpret_cast<const uint2*>(g_xt + gbase);
    float2 v0 = __half22float2(*reinterpret_cast<__half2*>(&pk.x));
    float2 v1 = __half22float2(*reinterpret_cast<__half2*>(&pk.y));
    tile[ty][4 * tx + 0] = v0.x;
    tile[ty][4 * tx + 1] = v0.y;
    tile[ty][4 * tx + 2] = v1.x;
    tile[ty][4 * tx + 3] = v1.y;
    __syncthreads();
    size_t idx = (((size_t)(b * Ln + l0 + ty)) * Nn + n0 + 4 * tx) >> 2;
    float4 xo = ((const float4*)x)[idx];
    float4 w;
    w.x = xo.x + tile[4 * tx + 0][ty];
    w.y = xo.y + tile[4 * tx + 1][ty];
    w.z = xo.z + tile[4 * tx + 2][ty];
    w.w = xo.w + tile[4 * tx + 3][ty];
    ((float4*)out)[idx] = w;
}

extern "C" void kernel_launch(void* const* d_in, const int* in_sizes, int n_in,
                              void* d_out, int out_size) {
    const float* x  = (const float*)d_in[0];
    const float* bb = (const float*)d_in[1];
    const float* w1 = (const float*)d_in[2];
    const float* b1 = (const float*)d_in[3];
    const float* w2 = (const float*)d_in[4];
    const float* b2 = (const float*)d_in[5];
    float* out = (float*)d_out;

    dim3 tb(8, 32);
    k_init<<<5, 256>>>(bb);
    k_transpose_in<<<dim3(128, 4, 64), tb>>>(x);
    k_fwd<<<NSER, 256>>>();
    k_mag<<<dim3(9, 64, 2), 256>>>();
    k_magred<<<513, 256>>>();
    k_gemm1a<<<dim3(33, KSPLIT), 256>>>(w1);
    k_gemm1b<<<dim3(9, 64), 256>>>(b1);
    k_gate2<<<64, 256>>>(w2, b2);
    k_inv<<<NSER, 256>>>();
    k_transpose_out<<<dim3(128, 4, 64), tb>>>(x, out);
}